// round 9
// baseline (speedup 1.0000x reference)
#include <cuda_runtime.h>
#include <cuda_fp16.h>
#include <math.h>

#define NMAX 100000
#define EMAX 1600000
#define C_IN 64
#define C_OUT 128
#define RPB 64
#define NB_SCAN ((NMAX + 1023) / 1024)

// Scratch (device globals — no allocations allowed)
__device__ float  g_y[(size_t)NMAX * C_IN];
__device__ float  g_x0[(size_t)NMAX * C_IN];
__device__ float  g_x1[(size_t)NMAX * C_IN];
__device__ __half g_xh[(size_t)NMAX * C_IN];   // fp16 copy of layer input (gather payload)
__device__ float  g_dinv[NMAX];
__device__ int    g_cnt[NMAX];
__device__ int    g_rowstart[NMAX + 1];
__device__ int2   g_edge[EMAX];                // {srcid, coef bits}
__device__ int    g_blocksum[NB_SCAN];
__device__ int    g_blockoff[NB_SCAN];

__device__ __forceinline__ int clampi(int v, int lo, int hi) {
    return v < lo ? lo : (v > hi ? hi : v);
}

// ---- f32x2 packed math helpers ----
__device__ __forceinline__ unsigned long long pack2(float lo, float hi) {
    unsigned long long r;
    asm("mov.b64 %0, {%1, %2};" : "=l"(r) : "f"(lo), "f"(hi));
    return r;
}
__device__ __forceinline__ void unpack2(unsigned long long v, float& lo, float& hi) {
    asm("mov.b64 {%0, %1}, %2;" : "=f"(lo), "=f"(hi) : "l"(v));
}
#define FMA_F32X2(d, a, b, c) \
    asm("fma.rn.f32x2 %0, %1, %2, %3;" : "=l"(d) : "l"(a), "l"(b), "l"(c))
#define ADD_F32X2(d, a, b) \
    asm("add.rn.f32x2 %0, %1, %2;" : "=l"(d) : "l"(a), "l"(b))

// ---------------- CSR build ----------------
__global__ void zero_cnt_kernel(int n) {
    int i = blockIdx.x * blockDim.x + threadIdx.x;
    if (i < n) g_cnt[i] = 0;
}
__global__ void count_kernel(const int* __restrict__ dst, int e, int n) {
    int i = blockIdx.x * blockDim.x + threadIdx.x;
    if (i < e) atomicAdd(&g_cnt[clampi(dst[i], 0, n - 1)], 1);
}
__global__ void dinv_kernel(int n) {
    int i = blockIdx.x * blockDim.x + threadIdx.x;
    if (i < n) g_dinv[i] = rsqrtf((float)g_cnt[i] + 1.0f);
}
__global__ void __launch_bounds__(1024) scan1_kernel(int n) {
    __shared__ int sm[1024];
    int i = blockIdx.x * 1024 + threadIdx.x;
    int v = (i < n) ? g_cnt[i] : 0;
    sm[threadIdx.x] = v;
    __syncthreads();
    #pragma unroll
    for (int off = 1; off < 1024; off <<= 1) {
        int t = (threadIdx.x >= off) ? sm[threadIdx.x - off] : 0;
        __syncthreads();
        sm[threadIdx.x] += t;
        __syncthreads();
    }
    if (i < n) g_rowstart[i] = sm[threadIdx.x] - v;
    if (threadIdx.x == 1023) g_blocksum[blockIdx.x] = sm[1023];
}
__global__ void scan2_kernel(int nb, int n) {
    int lane = threadIdx.x;
    int carry = 0;
    for (int base = 0; base < nb; base += 32) {
        int v = (base + lane < nb) ? g_blocksum[base + lane] : 0;
        int incl = v;
        #pragma unroll
        for (int off = 1; off < 32; off <<= 1) {
            int t = __shfl_up_sync(0xffffffffu, incl, off);
            if (lane >= off) incl += t;
        }
        if (base + lane < nb) g_blockoff[base + lane] = carry + incl - v;
        carry += __shfl_sync(0xffffffffu, incl, 31);
    }
    if (lane == 0) g_rowstart[n] = carry;
}
__global__ void __launch_bounds__(1024) scan3_kernel(int n) {
    int i = blockIdx.x * 1024 + threadIdx.x;
    if (i < n) g_rowstart[i] += g_blockoff[blockIdx.x];
}
__global__ void fill_kernel(const int* __restrict__ src,
                            const int* __restrict__ dst, int e, int n) {
    int i = blockIdx.x * blockDim.x + threadIdx.x;
    if (i >= e) return;
    int s = clampi(src[i], 0, n - 1);
    int d = clampi(dst[i], 0, n - 1);
    int pos = g_rowstart[d] + atomicAdd(&g_cnt[d], 1);
    g_edge[pos] = make_int2(s, __float_as_int(g_dinv[s] * g_dinv[d]));
}

// ---------------- fp16 convert (layer-0 input) ----------------
__global__ void tohalf_kernel(const float* __restrict__ xin, int total2) {
    int i = blockIdx.x * blockDim.x + threadIdx.x;
    if (i < total2) {
        const float2 v = reinterpret_cast<const float2*>(xin)[i];
        reinterpret_cast<__half2*>(g_xh)[i] = __float22half2_rn(v);
    }
}

// ---------------- aggregate in x-space (64 ch), fp16 gather -------------
// one warp per node; 4 edges in parallel (8 lanes each, LDG.128 = 128-B half row).
__global__ void __launch_bounds__(256)
agg_kernel(const float* __restrict__ xin, int n) {
    int node = (blockIdx.x * blockDim.x + threadIdx.x) >> 5;
    if (node >= n) return;
    int lane = threadIdx.x & 31;
    int sub = lane >> 3;     // edge slot 0..3
    int hl  = lane & 7;      // channel group: ch 8*hl .. 8*hl+7

    const float4* xh4 = reinterpret_cast<const float4*>(g_xh);  // 8 halves per float4

    float r[8] = {0.f, 0.f, 0.f, 0.f, 0.f, 0.f, 0.f, 0.f};

    int e0 = g_rowstart[node], e1 = g_rowstart[node + 1];
    #pragma unroll 2
    for (int t = e0 + sub; t < e1; t += 4) {
        int2 ed = __ldg(&g_edge[t]);                 // broadcast within 8-lane group
        float c = __int_as_float(ed.y);
        float4 raw = __ldg(&xh4[(size_t)ed.x * 8 + hl]);
        const __half2* hp = reinterpret_cast<const __half2*>(&raw);
        float2 v0 = __half22float2(hp[0]);
        float2 v1 = __half22float2(hp[1]);
        float2 v2 = __half22float2(hp[2]);
        float2 v3 = __half22float2(hp[3]);
        r[0] = fmaf(v0.x, c, r[0]); r[1] = fmaf(v0.y, c, r[1]);
        r[2] = fmaf(v1.x, c, r[2]); r[3] = fmaf(v1.y, c, r[3]);
        r[4] = fmaf(v2.x, c, r[4]); r[5] = fmaf(v2.y, c, r[5]);
        r[6] = fmaf(v3.x, c, r[6]); r[7] = fmaf(v3.y, c, r[7]);
    }
    __syncwarp();
    #pragma unroll
    for (int i = 0; i < 8; i++) {
        r[i] += __shfl_xor_sync(0xffffffffu, r[i], 8);
        r[i] += __shfl_xor_sync(0xffffffffu, r[i], 16);
    }

    // self-loop (f32) + store y (lanes 0..7 only)
    if (sub == 0) {
        float dv = g_dinv[node], s2 = dv * dv;
        const float4* x4 = reinterpret_cast<const float4*>(xin);
        float4 xs0 = __ldg(&x4[(size_t)node * 16 + 2 * hl]);
        float4 xs1 = __ldg(&x4[(size_t)node * 16 + 2 * hl + 1]);
        float4 o0, o1;
        o0.x = fmaf(xs0.x, s2, r[0]); o0.y = fmaf(xs0.y, s2, r[1]);
        o0.z = fmaf(xs0.z, s2, r[2]); o0.w = fmaf(xs0.w, s2, r[3]);
        o1.x = fmaf(xs1.x, s2, r[4]); o1.y = fmaf(xs1.y, s2, r[5]);
        o1.z = fmaf(xs1.z, s2, r[6]); o1.w = fmaf(xs1.w, s2, r[7]);
        float4* y4 = reinterpret_cast<float4*>(g_y);
        y4[(size_t)node * 16 + 2 * hl]     = o0;
        y4[(size_t)node * 16 + 2 * hl + 1] = o1;
    }
}

// ---------------- packed GEMM + bias + GLU + residual ----------------
// 128 threads: thread j owns col pair (c, c+64); also writes fp16 copy for next layer.
__global__ void __launch_bounds__(128)
gemm_glu_kernel(const float* __restrict__ xin, float* __restrict__ xout,
                const float* __restrict__ W, const float* __restrict__ b,
                int n) {
    __shared__ unsigned long long ysp[RPB][C_IN];   // 32 KB: pack2(y,y)

    const int j = threadIdx.x;
    const int c = j & 63;
    const int q = j >> 6;                 // 0 or 1
    const int row0 = blockIdx.x * RPB;

    #pragma unroll
    for (int t = j; t < RPB * C_IN; t += 128) {
        int r = t >> 6, k = t & 63;
        int row = row0 + r;
        float v = (row < n) ? g_y[(size_t)row * C_IN + k] : 0.0f;
        ysp[r][k] = pack2(v, v);
    }

    unsigned long long wp[C_IN];
    #pragma unroll
    for (int k = 0; k < C_IN; k++)
        wp[k] = pack2(W[k * C_OUT + c], W[k * C_OUT + c + 64]);
    const unsigned long long bb = pack2(b[c], b[c + 64]);

    __syncthreads();

    #pragma unroll 2
    for (int rr = 0; rr < RPB / 2; rr++) {
        int r = q * (RPB / 2) + rr;
        int row = row0 + r;
        const ulonglong2* yv = reinterpret_cast<const ulonglong2*>(&ysp[r][0]);
        unsigned long long a0 = bb, a1 = 0ull;
        #pragma unroll
        for (int k2 = 0; k2 < 32; k2++) {
            ulonglong2 yy = yv[k2];               // LDS.128 broadcast
            FMA_F32X2(a0, yy.x, wp[2 * k2 + 0], a0);
            FMA_F32X2(a1, yy.y, wp[2 * k2 + 1], a1);
        }
        unsigned long long at;
        ADD_F32X2(at, a0, a1);
        float av, gv;
        unpack2(at, av, gv);
        if (row < n) {
            float sig = 1.0f / (1.0f + expf(-gv));
            float out = fmaf(av, sig, xin[(size_t)row * C_IN + c]);
            xout[(size_t)row * C_IN + c] = out;
            g_xh[(size_t)row * C_IN + c] = __float2half_rn(out);  // next layer's gather payload
        }
    }
}

extern "C" void kernel_launch(void* const* d_in, const int* in_sizes, int n_in,
                              void* d_out, int out_size) {
    // Identify inputs by SIZE:
    //   x: == out_size (6.4M f32); edge_index: largest rest (3.2M i32);
    //   Ws: next (24576 f32); bs: smallest (384 f32)
    const float* x = nullptr; const float* Ws = nullptr; const float* bs = nullptr;
    const int* ei = nullptr;
    int ei_elems = 0, Ws_elems = 0;
    int used[16] = {0};
    for (int i = 0; i < n_in; i++)
        if (!x && in_sizes[i] == out_size) { x = (const float*)d_in[i]; used[i] = 1; break; }
    {
        int best = -1, bsz = -1;
        for (int i = 0; i < n_in; i++)
            if (!used[i] && in_sizes[i] > bsz) { bsz = in_sizes[i]; best = i; }
        ei = (const int*)d_in[best]; ei_elems = bsz; used[best] = 1;
    }
    {
        int best = -1, bsz = -1;
        for (int i = 0; i < n_in; i++)
            if (!used[i] && in_sizes[i] > bsz) { bsz = in_sizes[i]; best = i; }
        Ws = (const float*)d_in[best]; Ws_elems = bsz; used[best] = 1;
    }
    for (int i = 0; i < n_in; i++)
        if (!used[i]) { bs = (const float*)d_in[i]; used[i] = 1; break; }

    const int n = out_size / C_IN;
    const int e = ei_elems / 2;
    const int L = Ws_elems / (C_IN * C_OUT);
    const int* src = ei;
    const int* dst = ei + e;
    const int nb = (n + 1023) / 1024;

    float *x0, *x1;
    cudaGetSymbolAddress((void**)&x0, g_x0);
    cudaGetSymbolAddress((void**)&x1, g_x1);

    // ---- CSR build (once per call) ----
    zero_cnt_kernel<<<(n + 255) / 256, 256>>>(n);
    count_kernel<<<(e + 255) / 256, 256>>>(dst, e, n);
    dinv_kernel<<<(n + 255) / 256, 256>>>(n);
    scan1_kernel<<<nb, 1024>>>(n);
    scan2_kernel<<<1, 32>>>(nb, n);
    scan3_kernel<<<nb, 1024>>>(n);
    zero_cnt_kernel<<<(n + 255) / 256, 256>>>(n);
    fill_kernel<<<(e + 255) / 256, 256>>>(src, dst, e, n);

    // fp16 copy of layer-0 input
    tohalf_kernel<<<(n * C_IN / 2 + 255) / 256, 256>>>(x, n * C_IN / 2);

    // ---- layers ----
    const float* xin = x;
    for (int l = 0; l < L; l++) {
        float* xout = (l == L - 1) ? (float*)d_out : ((l & 1) ? x1 : x0);
        agg_kernel<<<(n * 32 + 255) / 256, 256>>>(xin, n);
        gemm_glu_kernel<<<(n + RPB - 1) / RPB, 128>>>(
            xin, xout, Ws + (size_t)l * C_IN * C_OUT, bs + (size_t)l * C_OUT, n);
        xin = xout;
    }
}

// round 10
// speedup vs baseline: 1.1176x; 1.1176x over previous
#include <cuda_runtime.h>
#include <math.h>

#define NMAX 100000
#define EMAX 1600000
#define C_IN 64
#define C_OUT 128
#define RPB 64
#define NB_SCAN ((NMAX + 1023) / 1024)

// Scratch (device globals — no allocations allowed)
__device__ float g_y[(size_t)NMAX * C_IN];
__device__ float g_x0[(size_t)NMAX * C_IN];
__device__ float g_x1[(size_t)NMAX * C_IN];
__device__ float g_dinv[NMAX];
__device__ int   g_cnt[NMAX];        // must be 0 at entry of every call (invariant)
__device__ int   g_fillctr[NMAX];    // bump allocators for fill
__device__ int   g_rowstart[NMAX + 1];
__device__ int2  g_edge[EMAX];       // {srcid, coef bits}
__device__ int   g_blocksum[NB_SCAN];
__device__ int   g_flag[NB_SCAN];    // must be 0 at entry (reset by fill_kernel)

__device__ __forceinline__ int clampi(int v, int lo, int hi) {
    return v < lo ? lo : (v > hi ? hi : v);
}

// ---- f32x2 packed math helpers ----
__device__ __forceinline__ unsigned long long pack2(float lo, float hi) {
    unsigned long long r;
    asm("mov.b64 %0, {%1, %2};" : "=l"(r) : "f"(lo), "f"(hi));
    return r;
}
__device__ __forceinline__ void unpack2(unsigned long long v, float& lo, float& hi) {
    asm("mov.b64 {%0, %1}, %2;" : "=f"(lo), "=f"(hi) : "l"(v));
}
#define FMA_F32X2(d, a, b, c) \
    asm("fma.rn.f32x2 %0, %1, %2, %3;" : "=l"(d) : "l"(a), "l"(b), "l"(c))
#define ADD_F32X2(d, a, b) \
    asm("add.rn.f32x2 %0, %1, %2;" : "=l"(d) : "l"(a), "l"(b))

// ---------------- launch 1: degree count ----------------
__global__ void count_kernel(const int* __restrict__ dst, int e, int n) {
    int i = blockIdx.x * blockDim.x + threadIdx.x;
    if (i < e) atomicAdd(&g_cnt[clampi(dst[i], 0, n - 1)], 1);
}

// ---------------- launch 2: scan (decoupled lookback) + dinv + reset ------
__global__ void __launch_bounds__(1024) scan_kernel(int n, int nb) {
    __shared__ int sm[1024];
    __shared__ int prefix_sm;
    const int b = blockIdx.x;
    const int i = b * 1024 + threadIdx.x;

    int v = (i < n) ? g_cnt[i] : 0;
    sm[threadIdx.x] = v;
    __syncthreads();
    #pragma unroll
    for (int off = 1; off < 1024; off <<= 1) {
        int t = (threadIdx.x >= off) ? sm[threadIdx.x - off] : 0;
        __syncthreads();
        sm[threadIdx.x] += t;
        __syncthreads();
    }
    const int total = sm[1023];

    // publish this block's total
    if (threadIdx.x == 0) {
        prefix_sm = 0;
        g_blocksum[b] = total;
        __threadfence();
        atomicExch(&g_flag[b], 1);
    }
    __syncthreads();

    // lookback: sum all predecessor block totals (blocks all resident: nb=98 < 148 SMs)
    int local = 0;
    for (int p = threadIdx.x; p < b; p += 1024) {
        while (atomicAdd(&g_flag[p], 0) == 0) { }
        local += g_blocksum[p];
    }
    if (local) atomicAdd(&prefix_sm, local);
    __syncthreads();
    const int prefix = prefix_sm;

    if (i < n) {
        int rs = prefix + sm[threadIdx.x] - v;   // exclusive
        g_rowstart[i] = rs;
        g_fillctr[i]  = rs;
        g_dinv[i]     = rsqrtf((float)v + 1.0f);
        g_cnt[i]      = 0;                       // restore invariant
    }
    if (b == nb - 1 && threadIdx.x == 0) g_rowstart[n] = prefix + total;
}

// ---------------- launch 3: fill edges (and reset lookback flags) ---------
__global__ void fill_kernel(const int* __restrict__ src,
                            const int* __restrict__ dst, int e, int n, int nb) {
    int i = blockIdx.x * blockDim.x + threadIdx.x;
    if (i < nb) g_flag[i] = 0;                   // restore invariant
    if (i >= e) return;
    int s = clampi(src[i], 0, n - 1);
    int d = clampi(dst[i], 0, n - 1);
    int pos = atomicAdd(&g_fillctr[d], 1);
    g_edge[pos] = make_int2(s, __float_as_int(g_dinv[s] * g_dinv[d]));
}

// ---------------- aggregate in x-space (64 ch) ----------------
// one warp per node; half-warps process edges t, t+1 in parallel.
__global__ void __launch_bounds__(256)
agg_kernel(const float* __restrict__ xin, int n) {
    int node = (blockIdx.x * blockDim.x + threadIdx.x) >> 5;
    if (node >= n) return;
    int lane = threadIdx.x & 31;
    int half = lane >> 4;
    int hl = lane & 15;

    const float4* x4 = reinterpret_cast<const float4*>(xin);
    float4 acc = make_float4(0.f, 0.f, 0.f, 0.f);

    int e0 = g_rowstart[node];
    int e1 = g_rowstart[node + 1];
    #pragma unroll 4
    for (int t = e0 + half; t < e1; t += 2) {
        int2 ed = __ldg(&g_edge[t]);            // broadcast within half-warp
        float c = __int_as_float(ed.y);
        float4 v = __ldg(&x4[(size_t)ed.x * 16 + hl]);
        acc.x = fmaf(v.x, c, acc.x);
        acc.y = fmaf(v.y, c, acc.y);
        acc.z = fmaf(v.z, c, acc.z);
        acc.w = fmaf(v.w, c, acc.w);
    }
    __syncwarp();
    acc.x += __shfl_xor_sync(0xffffffffu, acc.x, 16);
    acc.y += __shfl_xor_sync(0xffffffffu, acc.y, 16);
    acc.z += __shfl_xor_sync(0xffffffffu, acc.z, 16);
    acc.w += __shfl_xor_sync(0xffffffffu, acc.w, 16);

    if (half == 0) {
        float dv = g_dinv[node], s2 = dv * dv;
        float4 xs = __ldg(&x4[(size_t)node * 16 + hl]);
        acc.x = fmaf(xs.x, s2, acc.x);
        acc.y = fmaf(xs.y, s2, acc.y);
        acc.z = fmaf(xs.z, s2, acc.z);
        acc.w = fmaf(xs.w, s2, acc.w);
        reinterpret_cast<float4*>(g_y)[(size_t)node * 16 + hl] = acc;
    }
}

// ---------------- packed GEMM + bias + GLU + residual ----------------
__global__ void __launch_bounds__(128)
gemm_glu_kernel(const float* __restrict__ xin, float* __restrict__ xout,
                const float* __restrict__ W, const float* __restrict__ b,
                int n) {
    __shared__ unsigned long long ysp[RPB][C_IN];   // 32 KB: pack2(y,y)

    const int j = threadIdx.x;
    const int c = j & 63;
    const int q = j >> 6;
    const int row0 = blockIdx.x * RPB;

    #pragma unroll
    for (int t = j; t < RPB * C_IN; t += 128) {
        int r = t >> 6, k = t & 63;
        int row = row0 + r;
        float v = (row < n) ? g_y[(size_t)row * C_IN + k] : 0.0f;
        ysp[r][k] = pack2(v, v);
    }

    unsigned long long wp[C_IN];
    #pragma unroll
    for (int k = 0; k < C_IN; k++)
        wp[k] = pack2(W[k * C_OUT + c], W[k * C_OUT + c + 64]);
    const unsigned long long bb = pack2(b[c], b[c + 64]);

    __syncthreads();

    #pragma unroll 2
    for (int rr = 0; rr < RPB / 2; rr++) {
        int r = q * (RPB / 2) + rr;
        int row = row0 + r;
        const ulonglong2* yv = reinterpret_cast<const ulonglong2*>(&ysp[r][0]);
        unsigned long long a0 = bb, a1 = 0ull;
        #pragma unroll
        for (int k2 = 0; k2 < 32; k2++) {
            ulonglong2 yy = yv[k2];               // LDS.128 broadcast
            FMA_F32X2(a0, yy.x, wp[2 * k2 + 0], a0);
            FMA_F32X2(a1, yy.y, wp[2 * k2 + 1], a1);
        }
        unsigned long long at;
        ADD_F32X2(at, a0, a1);
        float av, gv;
        unpack2(at, av, gv);
        if (row < n) {
            float sig = 1.0f / (1.0f + expf(-gv));
            xout[(size_t)row * C_IN + c] =
                fmaf(av, sig, xin[(size_t)row * C_IN + c]);
        }
    }
}

extern "C" void kernel_launch(void* const* d_in, const int* in_sizes, int n_in,
                              void* d_out, int out_size) {
    // Identify inputs by SIZE:
    //   x: == out_size (6.4M f32); edge_index: largest rest (3.2M i32);
    //   Ws: next (24576 f32); bs: smallest (384 f32)
    const float* x = nullptr; const float* Ws = nullptr; const float* bs = nullptr;
    const int* ei = nullptr;
    int ei_elems = 0, Ws_elems = 0;
    int used[16] = {0};
    for (int i = 0; i < n_in; i++)
        if (!x && in_sizes[i] == out_size) { x = (const float*)d_in[i]; used[i] = 1; break; }
    {
        int best = -1, bsz = -1;
        for (int i = 0; i < n_in; i++)
            if (!used[i] && in_sizes[i] > bsz) { bsz = in_sizes[i]; best = i; }
        ei = (const int*)d_in[best]; ei_elems = bsz; used[best] = 1;
    }
    {
        int best = -1, bsz = -1;
        for (int i = 0; i < n_in; i++)
            if (!used[i] && in_sizes[i] > bsz) { bsz = in_sizes[i]; best = i; }
        Ws = (const float*)d_in[best]; Ws_elems = bsz; used[best] = 1;
    }
    for (int i = 0; i < n_in; i++)
        if (!used[i]) { bs = (const float*)d_in[i]; used[i] = 1; break; }

    const int n = out_size / C_IN;
    const int e = ei_elems / 2;
    const int L = Ws_elems / (C_IN * C_OUT);
    const int* src = ei;
    const int* dst = ei + e;
    const int nb = (n + 1023) / 1024;

    float *x0, *x1;
    cudaGetSymbolAddress((void**)&x0, g_x0);
    cudaGetSymbolAddress((void**)&x1, g_x1);

    // ---- CSR build: 3 launches ----
    count_kernel<<<(e + 255) / 256, 256>>>(dst, e, n);       // launch 1
    scan_kernel<<<nb, 1024>>>(n, nb);                        // launch 2
    fill_kernel<<<(e + 255) / 256, 256>>>(src, dst, e, n, nb); // launch 3

    // ---- layers (agg of layer 0 is launch 4 -> gets profiled) ----
    const float* xin = x;
    for (int l = 0; l < L; l++) {
        float* xout = (l == L - 1) ? (float*)d_out : ((l & 1) ? x1 : x0);
        agg_kernel<<<(n * 32 + 255) / 256, 256>>>(xin, n);
        gemm_glu_kernel<<<(n + RPB - 1) / RPB, 128>>>(
            xin, xout, Ws + (size_t)l * C_IN * C_OUT, bs + (size_t)l * C_OUT, n);
        xin = xout;
    }
}